// round 15
// baseline (speedup 1.0000x reference)
#include <cuda_runtime.h>
#include <cstdint>

#define HID   64
#define NVEC  16384
#define NB    8192

// bot/top (s-product + eta*(h@W2+b2)): g_bt[n][k], k<8192 bot, >=8192 top
__device__ float g_bt[128 * NVEC];   // 8 MB

// ---- packed fp32x2 helpers ----
__device__ __forceinline__ unsigned long long pack2(float x, float y) {
    unsigned long long d;
    asm("mov.b64 %0, {%1, %2};" : "=l"(d) : "f"(x), "f"(y));
    return d;
}
__device__ __forceinline__ void unpack2(unsigned long long d, float& x, float& y) {
    asm("mov.b64 {%0, %1}, %2;" : "=f"(x), "=f"(y) : "l"(d));
}
__device__ __forceinline__ unsigned long long fma2(unsigned long long a,
                                                   unsigned long long b,
                                                   unsigned long long c) {
    unsigned long long d;
    asm("fma.rn.f32x2 %0, %1, %2, %3;" : "=l"(d) : "l"(a), "l"(b), "l"(c));
    return d;
}

__device__ __forceinline__ void cp_async16(uint32_t dst, const void* src) {
    asm volatile("cp.async.cg.shared.global [%0], [%1], 16;" :: "r"(dst), "l"(src));
}
#define COMMIT() asm volatile("cp.async.commit_group;")
#define WAITG(N) asm volatile("cp.async.wait_group " #N ";")

// ---------------------------------------------------------------------------
// Kernel A: fused GEMM + bot/top build (R7 structure, mask-based H).
// grid = (16 slabs, 8 sample-groups) = 128 blocks, 256 threads.
// slab<8: x=slab, bot half; slab>=8: x=slab-8, top half.
// Thread owns k4 = slab*1024 + tid*4 for 16 samples.
// ---------------------------------------------------------------------------
__global__ void __launch_bounds__(256) fused_gemm_build(
    const int*   __restrict__ cfg,
    const float* __restrict__ A,
    const float* __restrict__ W1,
    const float* __restrict__ b1,
    const float* __restrict__ W2,
    const float* __restrict__ b2)
{
    __shared__ unsigned long long sh_hd[16 * HID];  // 8 KB {h,h}
    __shared__ float    sh_s[16 * 512];             // 32 KB: 2 slices x 256 / sample
    __shared__ unsigned sh_mask[16];                // cfg bitmasks

    const int tid   = threadIdx.x;
    const int slab  = blockIdx.x;
    const int n0    = blockIdx.y * 16;
    const int xx    = slab & 7;
    const int isTop = slab >> 3;
    const int ybase = isTop * 2;
    const int k4    = slab * 1024 + tid * 4;

    // cfg bitmasks (cfg values are 0/1)
    if (tid < 16) {
        const int* crow = cfg + (n0 + tid) * 32;
        unsigned m = 0;
        #pragma unroll
        for (int i = 0; i < 32; i++) m |= ((unsigned)crow[i] & 1u) << i;
        sh_mask[tid] = m;
    }
    __syncthreads();

    // Gather the two needed A-slices per sample (8192 floats, 32/thread)
    const float2* A2 = (const float2*)A;
    #pragma unroll
    for (int q = 0; q < 32; q++) {
        const int m   = q * 256 + tid;       // 0..8191
        const int s   = m >> 9;
        const int sl  = (m >> 8) & 1;
        const int idx = m & 255;
        const float2 a = A2[(xx * 4 + ybase + sl) * 256 + idx];
        const int bit = xx * 4 + ybase + sl;
        sh_s[m] = ((sh_mask[s] >> bit) & 1u) ? a.y : a.x;
    }

    // H = relu(cfg@W1+b1) via predicated adds (exact: skipping *0 == adding 0)
    {
        const int o  = tid & 63;
        const int sq = tid >> 6;             // 0..3 -> samples sq, sq+4, sq+8, sq+12
        const unsigned m0 = sh_mask[sq + 0];
        const unsigned m1 = sh_mask[sq + 4];
        const unsigned m2 = sh_mask[sq + 8];
        const unsigned m3 = sh_mask[sq + 12];
        const float bb = b1[o];
        float a0 = bb, a1 = bb, a2 = bb, a3 = bb;
        #pragma unroll
        for (int i = 0; i < 32; i++) {
            const float wv = W1[i * HID + o];   // coalesced, L1-hot
            if ((m0 >> i) & 1u) a0 += wv;
            if ((m1 >> i) & 1u) a1 += wv;
            if ((m2 >> i) & 1u) a2 += wv;
            if ((m3 >> i) & 1u) a3 += wv;
        }
        a0 = fmaxf(a0, 0.f); a1 = fmaxf(a1, 0.f);
        a2 = fmaxf(a2, 0.f); a3 = fmaxf(a3, 0.f);
        sh_hd[(sq + 0)  * HID + o] = pack2(a0, a0);
        sh_hd[(sq + 4)  * HID + o] = pack2(a1, a1);
        sh_hd[(sq + 8)  * HID + o] = pack2(a2, a2);
        sh_hd[(sq + 12) * HID + o] = pack2(a3, a3);
    }
    __syncthreads();

    // GEMM: acc[s*2+p] packed over k-pairs
    unsigned long long acc[32];
    #pragma unroll
    for (int q = 0; q < 32; q++) acc[q] = 0ull;

    #pragma unroll 4
    for (int jq = 0; jq < 16; jq++) {
        const int j0 = jq * 4;
        const float4 w0 = *(const float4*)(W2 + (j0 + 0) * NVEC + k4);
        const float4 w1 = *(const float4*)(W2 + (j0 + 1) * NVEC + k4);
        const float4 w2 = *(const float4*)(W2 + (j0 + 2) * NVEC + k4);
        const float4 w3 = *(const float4*)(W2 + (j0 + 3) * NVEC + k4);
        const unsigned long long w0lo = pack2(w0.x, w0.y), w0hi = pack2(w0.z, w0.w);
        const unsigned long long w1lo = pack2(w1.x, w1.y), w1hi = pack2(w1.z, w1.w);
        const unsigned long long w2lo = pack2(w2.x, w2.y), w2hi = pack2(w2.z, w2.w);
        const unsigned long long w3lo = pack2(w3.x, w3.y), w3hi = pack2(w3.z, w3.w);

        #pragma unroll
        for (int s = 0; s < 16; s++) {
            const ulonglong2 hd01 = *(const ulonglong2*)(sh_hd + s * HID + j0);
            const ulonglong2 hd23 = *(const ulonglong2*)(sh_hd + s * HID + j0 + 2);
            unsigned long long a0 = acc[s * 2 + 0];
            unsigned long long a1 = acc[s * 2 + 1];
            a0 = fma2(hd01.x, w0lo, a0);  a1 = fma2(hd01.x, w0hi, a1);
            a0 = fma2(hd01.y, w1lo, a0);  a1 = fma2(hd01.y, w1hi, a1);
            a0 = fma2(hd23.x, w2lo, a0);  a1 = fma2(hd23.x, w2hi, a1);
            a0 = fma2(hd23.y, w3lo, a0);  a1 = fma2(hd23.y, w3hi, a1);
            acc[s * 2 + 0] = a0;
            acc[s * 2 + 1] = a1;
        }
    }

    // Epilogue: add s-product, write bt (4 k per thread, 16 samples)
    const int idx = tid * 4;
    const int i  = idx >> 6;
    const int j  = (idx >> 2) & 15;
    const int l = i >> 2, L = i & 3, r = j >> 2, R = j & 3;
    const float4 bk  = *(const float4*)(b2 + k4);
    const float  eta = 0.001f;

    if (!isTop) {
        #pragma unroll
        for (int s = 0; s < 16; s++) {
            float4 cr;
            unpack2(acc[s * 2 + 0], cr.x, cr.y);
            unpack2(acc[s * 2 + 1], cr.z, cr.w);
            cr.x += bk.x; cr.y += bk.y; cr.z += bk.z; cr.w += bk.w;

            const float* sa = sh_s + s * 512;        // s0 slice
            const float* sb = sh_s + s * 512 + 256;  // s1 slice
            const float4  a0 = *(const float4*)(sa + l * 64 + r * 16);
            const float4* b4 = (const float4*)(sb + L * 64 + R * 16);
            const float4 b0 = b4[0], b1v = b4[1], b2v = b4[2], b3v = b4[3];
            float4 o4;
            o4.x = fmaf(a0.x, b0.x, fmaf(a0.y, b1v.x, fmaf(a0.z, b2v.x, fmaf(a0.w, b3v.x, eta * cr.x))));
            o4.y = fmaf(a0.x, b0.y, fmaf(a0.y, b1v.y, fmaf(a0.z, b2v.y, fmaf(a0.w, b3v.y, eta * cr.y))));
            o4.z = fmaf(a0.x, b0.z, fmaf(a0.y, b1v.z, fmaf(a0.z, b2v.z, fmaf(a0.w, b3v.z, eta * cr.z))));
            o4.w = fmaf(a0.x, b0.w, fmaf(a0.y, b1v.w, fmaf(a0.z, b2v.w, fmaf(a0.w, b3v.w, eta * cr.w))));
            *(float4*)(g_bt + (n0 + s) * NVEC + k4) = o4;
        }
    } else {
        #pragma unroll
        for (int s = 0; s < 16; s++) {
            float4 cr;
            unpack2(acc[s * 2 + 0], cr.x, cr.y);
            unpack2(acc[s * 2 + 1], cr.z, cr.w);
            cr.x += bk.x; cr.y += bk.y; cr.z += bk.z; cr.w += bk.w;

            const float* sa = sh_s + s * 512;        // s2 slice
            const float* sb = sh_s + s * 512 + 256;  // s3 slice
            const float4* c4 = (const float4*)(sa + l * 64 + r * 16);
            const float4 c0 = c4[0], c1 = c4[1], c2 = c4[2], c3 = c4[3];
            const float e0 = sb[L * 64 + R * 16 + 0];
            const float e1 = sb[L * 64 + R * 16 + 4];
            const float e2 = sb[L * 64 + R * 16 + 8];
            const float e3 = sb[L * 64 + R * 16 + 12];
            float4 o4;
            o4.x = fmaf(c0.x, e0, fmaf(c0.y, e1, fmaf(c0.z, e2, fmaf(c0.w, e3, eta * cr.x))));
            o4.y = fmaf(c1.x, e0, fmaf(c1.y, e1, fmaf(c1.z, e2, fmaf(c1.w, e3, eta * cr.y))));
            o4.z = fmaf(c2.x, e0, fmaf(c2.y, e1, fmaf(c2.z, e2, fmaf(c2.w, e3, eta * cr.z))));
            o4.w = fmaf(c3.x, e0, fmaf(c3.y, e1, fmaf(c3.z, e2, fmaf(c3.w, e3, eta * cr.w))));
            *(float4*)(g_bt + (n0 + s) * NVEC + k4) = o4;
        }
    }
}

// ---------------------------------------------------------------------------
// Kernel B: scan only. 128 blocks x 512 threads, all 8 tiles prefetched.
// De-shuffled steps: lane = (I|J = lane&15, up = lane>>4 picks U-pair).
// step1: zero shuffles. step2: one shfl_xor(16). 1 block barrier per x.
// ---------------------------------------------------------------------------
#define B_SMEM_FLOATS (8 * 2048 + 1024 + 1024)   // buf | sh_t | vd(512 u64)

__global__ void __launch_bounds__(512) scan_kernel(float* __restrict__ out)
{
    extern __shared__ float sm[];
    float* buf  = sm;                                   // 8 tiles x 2048 [bot|top]
    float* sh_t = sm + 16384;                           // t[j][I][U]
    unsigned long long* sh_vd = (unsigned long long*)(sm + 17408);  // 2 x 256

    const int n   = blockIdx.x;
    const int tid = threadIdx.x;
    const float* src = g_bt + n * NVEC;

    const int half = tid >> 8;
    const int e4   = (tid & 255) * 4;
    const uint32_t dst0 = (uint32_t)__cvta_generic_to_shared(buf + half * 1024 + e4);

    #pragma unroll
    for (int p = 0; p < 8; p++) {
        cp_async16(dst0 + p * 2048 * 4, src + p * 1024 + half * 8192 + e4);
        COMMIT();
    }

    if (tid < 256) {
        const float v = (tid == 0) ? 1.0f : 0.0f;
        sh_vd[tid] = pack2(v, v);
    }

    const int w    = tid >> 5;
    const int lane = tid & 31;
    const int I15  = lane & 15;        // I (step1) / J (step2)
    const int up   = lane >> 4;        // U-pair: 0 -> U0,U1 ; 1 -> U2,U3

    #pragma unroll
    for (int x = 0; x < 8; x++) {
        if      (x == 0) WAITG(7);
        else if (x == 1) WAITG(6);
        else if (x == 2) WAITG(5);
        else if (x == 3) WAITG(4);
        else if (x == 4) WAITG(3);
        else if (x == 5) WAITG(2);
        else if (x == 6) WAITG(1);
        else             WAITG(0);
        __syncthreads();

        const float* bt = buf + x * 2048;
        const float* tp = bt + 1024;
        const unsigned long long* vcur  = sh_vd + (x & 1) * 256;
        unsigned long long*       vnext = sh_vd + ((x & 1) ^ 1) * 256;

        // step1: t[I][up-pair] = sum_i v[i,I] * bot[i*64 + w*4 + up*2 ..]
        // No shuffles: each thread owns a full (I, U-pair) strip.
        {
            unsigned long long a = 0ull;
            #pragma unroll
            for (int i = 0; i < 16; i++) {
                const unsigned long long bb =
                    *(const unsigned long long*)(bt + i * 64 + w * 4 + up * 2);
                a = fma2(bb, vcur[i * 16 + I15], a);
            }
            *(unsigned long long*)(sh_t + w * 64 + I15 * 4 + up * 2) = a;
        }
        __syncwarp();

        // step2: v'[w,J] = sum_{I,U} t[I,U] * top[I*64 + J*4 + U]
        {
            unsigned long long c = 0ull;
            #pragma unroll
            for (int I = 0; I < 16; I++) {
                const unsigned long long tt =
                    *(const unsigned long long*)(sh_t + w * 64 + I * 4 + up * 2);
                const unsigned long long pp =
                    *(const unsigned long long*)(tp + I * 64 + I15 * 4 + up * 2);
                c = fma2(tt, pp, c);
            }
            float s0, s1;
            unpack2(c, s0, s1);
            float nv = s0 + s1;
            nv += __shfl_xor_sync(0xffffffffu, nv, 16);
            if (lane < 16) vnext[w * 16 + I15] = pack2(nv, nv);
        }
        __syncthreads();
    }

    if (tid == 0) {
        float a, b;
        unpack2(sh_vd[0], a, b);   // x=7 wrote half 0
        out[n] = a;
    }
}

// ---------------------------------------------------------------------------
extern "C" void kernel_launch(void* const* d_in, const int* in_sizes, int n_in,
                              void* d_out, int out_size)
{
    const int*   cfg = (const int*)  d_in[0];
    const float* A   = (const float*)d_in[1];
    const float* W1  = (const float*)d_in[2];
    const float* b1  = (const float*)d_in[3];
    const float* W2  = (const float*)d_in[4];
    const float* b2  = (const float*)d_in[5];
    float* out = (float*)d_out;

    cudaFuncSetAttribute(scan_kernel,
                         cudaFuncAttributeMaxDynamicSharedMemorySize,
                         B_SMEM_FLOATS * 4);

    fused_gemm_build<<<dim3(16, 8), 256>>>(cfg, A, W1, b1, W2, b2);
    scan_kernel<<<128, 512, B_SMEM_FLOATS * 4>>>(out);
}